// round 13
// baseline (speedup 1.0000x reference)
#include <cuda_runtime.h>
#include <math.h>

// InterfaceBoundaryLoss: B=4, H=W=2048, DX=DY=0.01, E_IN=2, CONST=1, WEIGHT=1.
//
// With a=h-1024, b=w-1024, dd=a^2+b^2:
//   interface <=> dd <  262144           (r < 512)
//   boundary  <=> 261122 <= dd <= 263168 (|r-512| < 1)
//
// R12 = R11 body (octant symmetry, coalesced lane map p=lane&3, hoisted
//       geometry, front-batched 24 loads -> one latency round, regs=40)
//     + single packed-u64 atomic tail PER BLOCK (46 blocks x 8 warps):
//       pack = (1<<55) | round(sum * 2^16). The add IS the arrival ticket:
//       the block whose return shows count==45 provably includes every other
//       block's add (each block's add precedes its own "ticket", which is the
//       same op) -> ret+mine is the global total. No atomicInc, no fence, no
//       exch on the critical store path (reset follows the store).

#define WW 2048
#define HWSZ (2048 * 2048)
#define TH  262144
#define LOQ 261122
#define HIQ 263168
#define NROWS 363
#define WARPS_PER_BLK 8
#define NBLOCKS ((NROWS + WARPS_PER_BLK - 1) / WARPS_PER_BLK)   // 46

#define CNT_SHIFT 55
#define SUM_MASK  ((1ULL << CNT_SHIFT) - 1ULL)
#define FP_SCALE  65536.0        // 2^16

__device__ unsigned long long g_pack = 0ULL;

__global__ void __launch_bounds__(WARPS_PER_BLK * 32, 1)
ibl_kernel(const float* __restrict__ s1, const float* __restrict__ s2,
           float* __restrict__ out, double invq)
{
    const int tid  = threadIdx.x;
    const int lane = tid & 31;
    const int wid  = tid >> 5;
    const int a    = blockIdx.x * WARPS_PER_BLK + wid;   // octant row

    float lacc = 0.0f;

    if (a < NROWS) {
        const int lo = LOQ - a * a;            // > 0 for a <= 362
        const int hi = HIQ - a * a;

        // branchless integer sqrt: sqrtf is within +-1 of the true root
        int bmax = (int)sqrtf((float)hi);
        bmax += ((bmax + 1) * (bmax + 1) <= hi);
        bmax -= (bmax * bmax > hi);
        int bminr = (int)sqrtf((float)lo);
        bminr += (bminr * bminr < lo);
        bminr -= ((bminr - 1) * (bminr - 1) >= lo);
        const int bmin = (bminr > a) ? bminr : a;   // octant: b >= a
        const int Wd   = bmax - bmin + 1;           // 1..4

        // lane -> (pixel-in-run, reflection); p fastest for coalescing
        const int p    = lane & 3;
        const int refl = lane >> 2;                 // 0..7
        const int sg1  = (refl & 1) ? -1 : 1;
        const int sg2  = (refl & 2) ? -1 : 1;
        const int sw   = refl >> 2;

        // ---- geometry: depends only on (a, b, refl); computed once ----
        const bool live = (p < Wd);
        const int  b    = bmin + (live ? p : 0);    // clamp dead slots
        bool nodup;
        if (a == 0)       nodup = sw ? (sg2 > 0) : (sg1 > 0);
        else if (a == b)  nodup = (sw == 0);
        else              nodup = true;
        const float w = (live && nodup) ? 1.0f : 0.0f;

        const int x0 = sw ? b : a;
        const int y0 = sw ? a : b;
        const int x  = sg1 * x0;                    // h - 1024
        const int y  = sg2 * y0;                    // w - 1024

        const int dd = x * x + y * y;
        const bool c  = dd < TH;
        const bool pu = ((((x - 1) * (x - 1) + y * y) < TH) == c);
        const bool pd = ((((x + 1) * (x + 1) + y * y) < TH) == c);
        const bool pl = (((x * x + (y - 1) * (y - 1)) < TH) == c);
        const bool pr = (((x * x + (y + 1) * (y + 1)) < TH) == c);
        const int voff = pu ? -WW : (pd ? WW : 0);  // 0 -> grad = 0
        const int hoff = pl ? -1  : (pr ? 1  : 0);

        const int idx0 = (x + 1024) * WW + (y + 1024);

        // ---- phase 1: issue ALL 24 loads before any arithmetic ----
        float o1[4], o1v[4], o1h[4], o2[4], o2v[4], o2h[4];
        #pragma unroll
        for (int bb = 0; bb < 4; ++bb) {
            const int idx = idx0 + bb * HWSZ;
            o1[bb]  = __ldg(s1 + idx);
            o1v[bb] = __ldg(s1 + idx + voff);
            o1h[bb] = __ldg(s1 + idx + hoff);
            o2[bb]  = __ldg(s2 + idx);
            o2v[bb] = __ldg(s2 + idx + voff);
            o2h[bb] = __ldg(s2 + idx + hoff);
        }

        // ---- phase 2: arithmetic ----
        float f = 0.0f;
        #pragma unroll
        for (int bb = 0; bb < 4; ++bb) {
            const float dv = o1[bb] - o2[bb];
            f = fmaf(dv, dv, f);
            float g, t;
            g = (o1[bb] - o1v[bb]) * 100.0f;
            t = fmaf(2.0f, g, -1.0f);  f = fmaf(t, t, f);
            g = (o1[bb] - o1h[bb]) * 100.0f;
            t = fmaf(2.0f, g, -1.0f);  f = fmaf(t, t, f);
            g = (o2[bb] - o2v[bb]) * 100.0f;
            t = fmaf(2.0f, g, -1.0f);  f = fmaf(t, t, f);
            g = (o2[bb] - o2h[bb]) * 100.0f;
            t = fmaf(2.0f, g, -1.0f);  f = fmaf(t, t, f);
        }
        lacc = w * f;
    }

    // ---- warp reduce (float) ----
    #pragma unroll
    for (int o = 16; o > 0; o >>= 1)
        lacc += __shfl_down_sync(0xffffffffu, lacc, o);

    __shared__ float sacc[WARPS_PER_BLK];
    if (lane == 0) sacc[wid] = lacc;
    __syncthreads();
    if (wid == 0 && lane < WARPS_PER_BLK) {
        lacc = sacc[lane];
        #pragma unroll
        for (int o = WARPS_PER_BLK / 2; o > 0; o >>= 1)
            lacc += __shfl_down_sync(0x000000ffu, lacc, o);
        if (lane == 0) {
            // single packed atomic: arrival count [55,64), fp sum [0,55)
            const unsigned long long mine =
                (1ULL << CNT_SHIFT) |
                (unsigned long long)((double)lacc * FP_SCALE + 0.5);
            const unsigned long long ret = atomicAdd(&g_pack, mine);
            if ((ret >> CNT_SHIFT) == (unsigned long long)(NBLOCKS - 1)) {
                // every block's add precedes its ticket == this same add, so
                // ret+mine contains all NBLOCKS contributions.
                const unsigned long long tot = (ret + mine) & SUM_MASK;
                out[0] = (float)((double)tot * invq);
                atomicExch(&g_pack, 0ULL);      // reset for next graph replay
            }
        }
    }
}

extern "C" void kernel_launch(void* const* d_in, const int* in_sizes, int n_in,
                              void* d_out, int out_size)
{
    (void)in_sizes; (void)n_in; (void)out_size;
    const float* s1 = (const float*)d_in[0];
    const float* s2 = (const float*)d_in[1];
    float* out = (float*)d_out;

    // nb (boundary-pixel count) is a pure function of the geometry: compute
    // exactly on host with the same integer logic.
    long long nb = 0;
    for (int a = -512; a <= 512; ++a) {
        const int lo = LOQ - a * a;
        const int hi = HIQ - a * a;
        if (hi < 0) continue;
        int bmax = (int)floor(sqrt((double)hi));
        while ((long long)(bmax + 1) * (bmax + 1) <= hi) ++bmax;
        while ((long long)bmax * bmax > hi) --bmax;
        int bmin = 0;
        if (lo > 0) {
            bmin = (int)ceil(sqrt((double)lo));
            while ((long long)bmin * bmin < lo) ++bmin;
            while (bmin > 0 && (long long)(bmin - 1) * (bmin - 1) >= lo) --bmin;
        }
        if (bmax >= bmin)
            nb += (lo > 0) ? 2LL * (bmax - bmin + 1) : (2LL * bmax + 1);
    }
    // invq = WEIGHT / (B * nb * 2^16)
    const double invq = 1.0 / (4.0 * (double)nb * FP_SCALE);

    ibl_kernel<<<NBLOCKS, WARPS_PER_BLK * 32>>>(s1, s2, out, invq);
}

// round 14
// speedup vs baseline: 1.3413x; 1.3413x over previous
#include <cuda_runtime.h>
#include <math.h>

// InterfaceBoundaryLoss: B=4, H=W=2048, DX=DY=0.01, E_IN=2, CONST=1, WEIGHT=1.
//
// With a=h-1024, b=w-1024, dd=a^2+b^2:
//   interface <=> dd <  262144           (r < 512)
//   boundary  <=> 261122 <= dd <= 263168 (|r-512| < 1)
//
// R13 = R11 body EXACTLY (91 blocks x 4 warps: octant symmetry, coalesced
//       lane map p=lane&3, hoisted geometry, front-batched 24 loads -> one
//       latency round, regs=40 — best measured kernel, 6.02us)
//     + R12 packed tail at 91-block depth: ONE u64 atomicAdd per block that
//       is both sum-accumulate and arrival ticket.
//       pack = (1<<55) | round(sum * 2^16); block seeing count==90 in the
//       return value provably holds the global total (its own add IS its
//       ticket). Store result, then reset off the critical path.

#define WW 2048
#define HWSZ (2048 * 2048)
#define TH  262144
#define LOQ 261122
#define HIQ 263168
#define NROWS 363
#define WARPS_PER_BLK 4
#define NBLOCKS ((NROWS + WARPS_PER_BLK - 1) / WARPS_PER_BLK)   // 91

#define CNT_SHIFT 55
#define SUM_MASK  ((1ULL << CNT_SHIFT) - 1ULL)
#define FP_SCALE  65536.0        // 2^16

__device__ unsigned long long g_pack = 0ULL;

__global__ void __launch_bounds__(WARPS_PER_BLK * 32, 1)
ibl_kernel(const float* __restrict__ s1, const float* __restrict__ s2,
           float* __restrict__ out, double invq)
{
    const int tid  = threadIdx.x;
    const int lane = tid & 31;
    const int wid  = tid >> 5;
    const int a    = blockIdx.x * WARPS_PER_BLK + wid;   // octant row

    float lacc = 0.0f;

    if (a < NROWS) {
        const int lo = LOQ - a * a;            // > 0 for a <= 362
        const int hi = HIQ - a * a;

        // branchless integer sqrt: sqrtf is within +-1 of the true root
        int bmax = (int)sqrtf((float)hi);
        bmax += ((bmax + 1) * (bmax + 1) <= hi);
        bmax -= (bmax * bmax > hi);
        int bminr = (int)sqrtf((float)lo);
        bminr += (bminr * bminr < lo);
        bminr -= ((bminr - 1) * (bminr - 1) >= lo);
        const int bmin = (bminr > a) ? bminr : a;   // octant: b >= a
        const int Wd   = bmax - bmin + 1;           // 1..4

        // lane -> (pixel-in-run, reflection); p fastest for coalescing
        const int p    = lane & 3;
        const int refl = lane >> 2;                 // 0..7
        const int sg1  = (refl & 1) ? -1 : 1;
        const int sg2  = (refl & 2) ? -1 : 1;
        const int sw   = refl >> 2;

        // ---- geometry: depends only on (a, b, refl); computed once ----
        const bool live = (p < Wd);
        const int  b    = bmin + (live ? p : 0);    // clamp dead slots
        bool nodup;
        if (a == 0)       nodup = sw ? (sg2 > 0) : (sg1 > 0);
        else if (a == b)  nodup = (sw == 0);
        else              nodup = true;
        const float w = (live && nodup) ? 1.0f : 0.0f;

        const int x0 = sw ? b : a;
        const int y0 = sw ? a : b;
        const int x  = sg1 * x0;                    // h - 1024
        const int y  = sg2 * y0;                    // w - 1024

        const int dd = x * x + y * y;
        const bool c  = dd < TH;
        const bool pu = ((((x - 1) * (x - 1) + y * y) < TH) == c);
        const bool pd = ((((x + 1) * (x + 1) + y * y) < TH) == c);
        const bool pl = (((x * x + (y - 1) * (y - 1)) < TH) == c);
        const bool pr = (((x * x + (y + 1) * (y + 1)) < TH) == c);
        const int voff = pu ? -WW : (pd ? WW : 0);  // 0 -> grad = 0
        const int hoff = pl ? -1  : (pr ? 1  : 0);

        const int idx0 = (x + 1024) * WW + (y + 1024);

        // ---- phase 1: issue ALL 24 loads before any arithmetic ----
        float o1[4], o1v[4], o1h[4], o2[4], o2v[4], o2h[4];
        #pragma unroll
        for (int bb = 0; bb < 4; ++bb) {
            const int idx = idx0 + bb * HWSZ;
            o1[bb]  = __ldg(s1 + idx);
            o1v[bb] = __ldg(s1 + idx + voff);
            o1h[bb] = __ldg(s1 + idx + hoff);
            o2[bb]  = __ldg(s2 + idx);
            o2v[bb] = __ldg(s2 + idx + voff);
            o2h[bb] = __ldg(s2 + idx + hoff);
        }

        // ---- phase 2: arithmetic ----
        float f = 0.0f;
        #pragma unroll
        for (int bb = 0; bb < 4; ++bb) {
            const float dv = o1[bb] - o2[bb];
            f = fmaf(dv, dv, f);
            float g, t;
            g = (o1[bb] - o1v[bb]) * 100.0f;
            t = fmaf(2.0f, g, -1.0f);  f = fmaf(t, t, f);
            g = (o1[bb] - o1h[bb]) * 100.0f;
            t = fmaf(2.0f, g, -1.0f);  f = fmaf(t, t, f);
            g = (o2[bb] - o2v[bb]) * 100.0f;
            t = fmaf(2.0f, g, -1.0f);  f = fmaf(t, t, f);
            g = (o2[bb] - o2h[bb]) * 100.0f;
            t = fmaf(2.0f, g, -1.0f);  f = fmaf(t, t, f);
        }
        lacc = w * f;
    }

    // ---- warp reduce (float) ----
    #pragma unroll
    for (int o = 16; o > 0; o >>= 1)
        lacc += __shfl_down_sync(0xffffffffu, lacc, o);

    __shared__ float sacc[WARPS_PER_BLK];
    if (lane == 0) sacc[wid] = lacc;
    __syncthreads();
    if (wid == 0 && lane < WARPS_PER_BLK) {
        lacc = sacc[lane];
        #pragma unroll
        for (int o = WARPS_PER_BLK / 2; o > 0; o >>= 1)
            lacc += __shfl_down_sync(0x0000000fu, lacc, o);
        if (lane == 0) {
            // single packed atomic: arrival count [55,64), fp sum [0,55)
            const unsigned long long mine =
                (1ULL << CNT_SHIFT) |
                (unsigned long long)((double)lacc * FP_SCALE + 0.5);
            const unsigned long long ret = atomicAdd(&g_pack, mine);
            if ((ret >> CNT_SHIFT) == (unsigned long long)(NBLOCKS - 1)) {
                // every block's add precedes its ticket == this same add, so
                // ret+mine contains all NBLOCKS contributions.
                const unsigned long long tot = (ret + mine) & SUM_MASK;
                out[0] = (float)((double)tot * invq);
                atomicExch(&g_pack, 0ULL);      // reset for next graph replay
            }
        }
    }
}

extern "C" void kernel_launch(void* const* d_in, const int* in_sizes, int n_in,
                              void* d_out, int out_size)
{
    (void)in_sizes; (void)n_in; (void)out_size;
    const float* s1 = (const float*)d_in[0];
    const float* s2 = (const float*)d_in[1];
    float* out = (float*)d_out;

    // nb (boundary-pixel count) is a pure function of the geometry: compute
    // exactly on host with the same integer logic.
    long long nb = 0;
    for (int a = -512; a <= 512; ++a) {
        const int lo = LOQ - a * a;
        const int hi = HIQ - a * a;
        if (hi < 0) continue;
        int bmax = (int)floor(sqrt((double)hi));
        while ((long long)(bmax + 1) * (bmax + 1) <= hi) ++bmax;
        while ((long long)bmax * bmax > hi) --bmax;
        int bmin = 0;
        if (lo > 0) {
            bmin = (int)ceil(sqrt((double)lo));
            while ((long long)bmin * bmin < lo) ++bmin;
            while (bmin > 0 && (long long)(bmin - 1) * (bmin - 1) >= lo) --bmin;
        }
        if (bmax >= bmin)
            nb += (lo > 0) ? 2LL * (bmax - bmin + 1) : (2LL * bmax + 1);
    }
    // invq = WEIGHT / (B * nb * 2^16)
    const double invq = 1.0 / (4.0 * (double)nb * FP_SCALE);

    ibl_kernel<<<NBLOCKS, WARPS_PER_BLK * 32>>>(s1, s2, out, invq);
}